// round 10
// baseline (speedup 1.0000x reference)
#include <cuda_runtime.h>
#include <cuda_fp16.h>
#include <cstdint>

// ShiftConv: shift -> 1x1 conv (GEMM M=50176,N=512,K=512) -> BN -> ReLU.
// Round 10: prepass transpose eliminated. g_Ah stays in [c][p] layout
// (streaming gather+convert, no smem), and the GEMM loads A fragments with
// ldmatrix.x4.trans from a [k][p] smem tile. B path / ring / epilogue = R9.

#define HDIM 28
#define HW   784
#define NPOS 50176
#define CCH  512
#define EPSV 1e-5f

#define MMA_F16(C, A, B) \
  asm volatile("mma.sync.aligned.m16n8k16.row.col.f32.f16.f16.f32 " \
    "{%0,%1,%2,%3}, {%4,%5,%6,%7}, {%8,%9}, {%0,%1,%2,%3};" \
    : "+f"((C)[0]), "+f"((C)[1]), "+f"((C)[2]), "+f"((C)[3]) \
    : "r"((A)[0]), "r"((A)[1]), "r"((A)[2]), "r"((A)[3]), \
      "r"((B)[0]), "r"((B)[1]))

#define LDSM4(R0, R1, R2, R3, addr) \
  asm volatile("ldmatrix.sync.aligned.m8n8.x4.shared.b16 {%0,%1,%2,%3}, [%4];" \
    : "=r"(R0), "=r"(R1), "=r"(R2), "=r"(R3) : "r"(addr))

#define LDSM4T(R0, R1, R2, R3, addr) \
  asm volatile("ldmatrix.sync.aligned.m8n8.x4.trans.shared.b16 {%0,%1,%2,%3}, [%4];" \
    : "=r"(R0), "=r"(R1), "=r"(R2), "=r"(R3) : "r"(addr))

#define CP16(dst, src) \
  asm volatile("cp.async.cg.shared.global [%0], [%1], 16;" :: "r"(dst), "l"(src))
#define CPCOMMIT() asm volatile("cp.async.commit_group;" ::: "memory")
#define CPWAIT(n)  asm volatile("cp.async.wait_group %0;" :: "n"(n) : "memory")

#define KC  64
// A tile: [k][p], 64 rows x 128 cols, stride 136 halves (272B: rows hit
// distinct 16B segments mod 128B -> trans-LDSM conflict-free)
#define PST 136
// B tile: [o][k], 128 rows x 64 cols, stride 72 halves (144B)
#define KST 72
#define NSTAGE 3
#define A_BYTES (KC * PST * 2)             // 17408
#define B_BYTES (128 * KST * 2)            // 18432
#define A_OFF 0
#define B_OFF A_BYTES
#define STAGE_BYTES (A_BYTES + B_BYTES)    // 35840
#define SMEM_TOTAL (NSTAGE * STAGE_BYTES)  // 107520

__device__ __half g_Wh[CCH * CCH];
__device__ __half g_Ah[(size_t)CCH * NPOS];   // shifted x, fp16, [c][p]

__device__ __forceinline__ uint32_t smem_u32(const void* p) {
    uint32_t a;
    asm("{ .reg .u64 t; cvta.to.shared.u64 t, %1; cvt.u32.u64 %0, t; }"
        : "=r"(a) : "l"(p));
    return a;
}

__global__ void conv_w_kernel(const float* __restrict__ Wm) {
    int i = blockIdx.x * 256 + threadIdx.x;
    g_Wh[i] = __float2half_rn(Wm[i]);
}

// Streaming shift-gather + fp16 convert, NO transpose: Ah[c][p] = fp16(
// x[b(p), c, shifted hw]). Read and write both coalesced over p.
__global__ __launch_bounds__(256)
void shift_x_kernel(const float* __restrict__ x) {
    const int p = blockIdx.x * 256 + threadIdx.x;   // 0..50175
    const int c = blockIdx.y;                        // 0..511
    const int g = c >> 7;

    int b  = p / HW;
    int hw = p - b * HW;
    int h  = hw / HDIM;
    int w  = hw - h * HDIM;
    int hs = h, ws = w;
    if      (g == 0) hs = (h + 1) % HDIM;
    else if (g == 1) hs = (h + HDIM - 1) % HDIM;
    else if (g == 2) ws = (w + 1) % HDIM;
    else             ws = (w + HDIM - 1) % HDIM;

    float v = x[(size_t)(b * CCH + c) * HW + hs * HDIM + ws];
    g_Ah[(size_t)c * NPOS + p] = __float2half_rn(v);
}

__global__ __launch_bounds__(256, 2)
void shiftconv_gemm(const float* __restrict__ gamma,
                    const float* __restrict__ beta,
                    const float* __restrict__ rmean,
                    const float* __restrict__ rvar,
                    float* __restrict__ out)
{
    extern __shared__ char dsm[];
    __shared__ float ssc[128], ssh[128];

    const int tid  = threadIdx.x;
    const int lane = tid & 31;
    const int wid  = tid >> 5;
    const int wm   = wid & 3;
    const int wn   = wid >> 2;
    const int g8   = lane >> 2;
    const int tig2 = (lane & 3) * 2;
    const int q    = lane >> 3;        // ldmatrix quad
    const int r8   = lane & 7;         // ldmatrix row within matrix

    const int pblock = blockIdx.x * 128;
    const int oblock = blockIdx.y * 128;

    if (tid < 128) {
        int o = oblock + tid;
        float sc = gamma[o] * rsqrtf(rvar[o] + EPSV);
        ssc[tid] = sc;
        ssh[tid] = beta[o] - rmean[o] * sc;
    }

    const uint32_t sdyn = smem_u32(dsm);

    // A (trans ldmatrix from [k][p] tile): matrix q covers
    // k rows (q>>1)*8 + r8, p col base (q&1)*8 -> regs {m0k0, m8k0, m0k8, m8k8}
    uint32_t aoff[2];
    #pragma unroll
    for (int mt = 0; mt < 2; mt++)
        aoff[mt] = (uint32_t)((((q >> 1) * 8 + r8) * PST
                               + wm * 32 + mt * 16 + (q & 1) * 8) * 2) + A_OFF;
    // B (non-trans from [o][k] tile), as in R7/R9
    uint32_t boff[4];
    #pragma unroll
    for (int np = 0; np < 4; np++)
        boff[np] = (uint32_t)(((wn * 64 + np * 16 + (q >> 1) * 8 + r8) * KST
                               + (q & 1) * 8) * 2) + B_OFF;

    // stage loader: A 64 rows x 256B, B 128 rows x 128B; 8 x 16B cp.async/thread
    auto load_stage = [&](int ch) {
        int kc = ch * KC;
        uint32_t st = sdyn + (ch % NSTAGE) * STAGE_BYTES;
        #pragma unroll
        for (int it = 0; it < 4; it++) {    // A: [k][p]
            int lin = tid + it * 256;
            int r = lin >> 4;          // k row 0..63
            int j = lin & 15;          // 16B chunk over p
            CP16(st + A_OFF + r * (PST * 2) + j * 16,
                 &g_Ah[(size_t)(kc + r) * NPOS + pblock + j * 8]);
        }
        #pragma unroll
        for (int it = 0; it < 4; it++) {    // B: [o][k]
            int lin = tid + it * 256;
            int r = lin >> 3;          // o row 0..127
            int j = lin & 7;           // 16B chunk over k
            CP16(st + B_OFF + r * (KST * 2) + j * 16,
                 &g_Wh[(size_t)(oblock + r) * CCH + kc + j * 8]);
        }
        CPCOMMIT();
    };

    float acc[2][8][4];
    #pragma unroll
    for (int mt = 0; mt < 2; mt++)
        #pragma unroll
        for (int nt = 0; nt < 8; nt++)
            #pragma unroll
            for (int rr = 0; rr < 4; rr++) acc[mt][nt][rr] = 0.0f;

    load_stage(0);
    load_stage(1);

    for (int ch = 0; ch < 8; ch++) {
        if (ch < 7) CPWAIT(1);
        else        CPWAIT(0);
        __syncthreads();   // compute(ch-1) fully done -> buffer (ch-1)%3 free

        if (ch < 6) load_stage(ch + 2);   // writes buffer (ch+2)%3 == (ch-1)%3

        const uint32_t st = sdyn + (ch % NSTAGE) * STAGE_BYTES;
        #pragma unroll
        for (int kk = 0; kk < KC; kk += 16) {
            const uint32_t ka = st + kk * (PST * 2);   // A advances by k rows
            const uint32_t kb = st + kk * 2;           // B advances along k
            uint32_t ah[2][4];
            #pragma unroll
            for (int mt = 0; mt < 2; mt++)
                LDSM4T(ah[mt][0], ah[mt][1], ah[mt][2], ah[mt][3], ka + aoff[mt]);
            uint32_t bh[8][2];
            #pragma unroll
            for (int np = 0; np < 4; np++)
                LDSM4(bh[2 * np][0], bh[2 * np][1],
                      bh[2 * np + 1][0], bh[2 * np + 1][1], kb + boff[np]);
            #pragma unroll
            for (int nt = 0; nt < 8; nt++)
                #pragma unroll
                for (int mt = 0; mt < 2; mt++)
                    MMA_F16(acc[mt][nt], ah[mt], bh[nt]);
        }
    }

    // Epilogue: BN + ReLU.
    #pragma unroll
    for (int mt = 0; mt < 2; mt++) {
        int p0 = pblock + wm * 32 + mt * 16 + g8;
        int p1 = p0 + 8;
        int b0 = p0 / HW, hw0 = p0 - b0 * HW;
        int b1 = p1 / HW, hw1 = p1 - b1 * HW;
        #pragma unroll
        for (int nt = 0; nt < 8; nt++) {
            int oo  = wn * 64 + nt * 8 + tig2;
            float sc0 = ssc[oo],     sh0 = ssh[oo];
            float sc1 = ssc[oo + 1], sh1 = ssh[oo + 1];
            int o0 = oblock + oo;
            float* q00 = out + ((size_t)(b0 * CCH + o0)) * HW + hw0;
            float* q01 = out + ((size_t)(b0 * CCH + o0 + 1)) * HW + hw0;
            float* q10 = out + ((size_t)(b1 * CCH + o0)) * HW + hw1;
            float* q11 = out + ((size_t)(b1 * CCH + o0 + 1)) * HW + hw1;
            *q00 = fmaxf(fmaf(acc[mt][nt][0], sc0, sh0), 0.0f);
            *q01 = fmaxf(fmaf(acc[mt][nt][1], sc1, sh1), 0.0f);
            *q10 = fmaxf(fmaf(acc[mt][nt][2], sc0, sh0), 0.0f);
            *q11 = fmaxf(fmaf(acc[mt][nt][3], sc1, sh1), 0.0f);
        }
    }
}

extern "C" void kernel_launch(void* const* d_in, const int* in_sizes, int n_in,
                              void* d_out, int out_size)
{
    const float* x     = (const float*)d_in[0];
    const float* Wm    = (const float*)d_in[1];
    const float* gamma = (const float*)d_in[2];
    const float* beta  = (const float*)d_in[3];
    const float* rmean = (const float*)d_in[4];
    const float* rvar  = (const float*)d_in[5];
    float* out = (float*)d_out;

    cudaFuncSetAttribute(shiftconv_gemm,
                         cudaFuncAttributeMaxDynamicSharedMemorySize, SMEM_TOTAL);

    conv_w_kernel<<<CCH * CCH / 256, 256>>>(Wm);
    dim3 pgrid(NPOS / 256, CCH);
    shift_x_kernel<<<pgrid, 256>>>(x);
    dim3 grid(392, 4);
    shiftconv_gemm<<<grid, 256, SMEM_TOTAL>>>(gamma, beta, rmean, rvar, out);
}

// round 11
// speedup vs baseline: 1.4000x; 1.4000x over previous
#include <cuda_runtime.h>
#include <cuda_fp16.h>
#include <cstdint>

// ShiftConv: shift -> 1x1 conv (GEMM M=50176,N=512,K=512) -> BN -> ReLU.
// Round 11: R9 base (best: 127us) with the k-step inner loop re-ordered to
// interleave B ldmatrix issues between MMA pairs (hides LDSM latency under
// tensor work instead of serializing 6 LDSM -> 16 MMA), and the 8-chunk
// mainloop fully unrolled. Layouts/prepass/epilogue byte-identical to R9.

#define HDIM 28
#define HW   784
#define CCH  512
#define EPSV 1e-5f

#define MMA_F16(C, A, B) \
  asm volatile("mma.sync.aligned.m16n8k16.row.col.f32.f16.f16.f32 " \
    "{%0,%1,%2,%3}, {%4,%5,%6,%7}, {%8,%9}, {%0,%1,%2,%3};" \
    : "+f"((C)[0]), "+f"((C)[1]), "+f"((C)[2]), "+f"((C)[3]) \
    : "r"((A)[0]), "r"((A)[1]), "r"((A)[2]), "r"((A)[3]), \
      "r"((B)[0]), "r"((B)[1]))

#define LDSM4(R0, R1, R2, R3, addr) \
  asm volatile("ldmatrix.sync.aligned.m8n8.x4.shared.b16 {%0,%1,%2,%3}, [%4];" \
    : "=r"(R0), "=r"(R1), "=r"(R2), "=r"(R3) : "r"(addr))

#define CP16(dst, src) \
  asm volatile("cp.async.cg.shared.global [%0], [%1], 16;" :: "r"(dst), "l"(src))
#define CPCOMMIT() asm volatile("cp.async.commit_group;" ::: "memory")
#define CPWAIT(n)  asm volatile("cp.async.wait_group %0;" :: "n"(n) : "memory")

// K-chunk 64; smem row stride 64 real + 8 pad fp16 (144B, 16B aligned)
#define KC  64
#define KST 72
#define NSTAGE 3
#define MAT_BYTES (128 * KST * 2)          // 18432
#define A_OFF 0
#define B_OFF MAT_BYTES
#define STAGE_BYTES (2 * MAT_BYTES)        // 36864
#define SMEM_TOTAL (NSTAGE * STAGE_BYTES)  // 110592

__device__ __half g_Wh[CCH * CCH];
__device__ __half g_Ah[(size_t)50176 * CCH];   // shifted x, fp16, [p][c]

__device__ __forceinline__ uint32_t smem_u32(const void* p) {
    uint32_t a;
    asm("{ .reg .u64 t; cvta.to.shared.u64 t, %1; cvt.u32.u64 %0, t; }"
        : "=r"(a) : "l"(p));
    return a;
}

// Merged prepass. Blocks [0,1024): W fp32->fp16 convert.
// Blocks [1024, 1024+784*8): shift-gather + transpose + fp16 convert of x.
__global__ __launch_bounds__(256)
void prepass_kernel(const float* __restrict__ x, const float* __restrict__ Wm) {
    __shared__ float tile[64][65];
    __shared__ int soff[64];
    const int tid = threadIdx.x;
    const int bid = blockIdx.x;

    if (bid < 1024) {
        int i = bid * 256 + tid;
        g_Wh[i] = __float2half_rn(Wm[i]);
        return;
    }

    const int b2 = bid - 1024;
    const int p0 = (b2 >> 3) * 64;
    const int c0 = (b2 & 7) * 64;
    const int g  = c0 >> 7;

    if (tid < 64) {
        int pg = p0 + tid;
        int b  = pg / HW;
        int hw = pg - b * HW;
        int h  = hw / HDIM;
        int w  = hw - h * HDIM;
        int hs = h, ws = w;
        if      (g == 0) hs = (h + 1) % HDIM;
        else if (g == 1) hs = (h + HDIM - 1) % HDIM;
        else if (g == 2) ws = (w + 1) % HDIM;
        else             ws = (w + HDIM - 1) % HDIM;
        soff[tid] = b * (CCH * HW) + hs * HDIM + ws;
    }
    __syncthreads();
    #pragma unroll
    for (int it = 0; it < 16; it++) {       // read coalesced over p
        int lin = tid + it * 256;
        int c = lin >> 6, p = lin & 63;
        tile[c][p] = x[(size_t)(c0 + c) * HW + soff[p]];
    }
    __syncthreads();
    #pragma unroll
    for (int it = 0; it < 16; it++) {       // write coalesced over c
        int lin = tid + it * 256;
        int p = lin >> 6, c = lin & 63;
        g_Ah[(size_t)(p0 + p) * CCH + c0 + c] = __float2half_rn(tile[c][p]);
    }
}

__global__ __launch_bounds__(256, 2)
void shiftconv_gemm(const float* __restrict__ gamma,
                    const float* __restrict__ beta,
                    const float* __restrict__ rmean,
                    const float* __restrict__ rvar,
                    float* __restrict__ out)
{
    extern __shared__ char dsm[];
    __shared__ float ssc[128], ssh[128];

    const int tid  = threadIdx.x;
    const int lane = tid & 31;
    const int wid  = tid >> 5;
    const int wm   = wid & 3;
    const int wn   = wid >> 2;
    const int g8   = lane >> 2;
    const int tig2 = (lane & 3) * 2;
    const int q    = lane >> 3;        // ldmatrix quad
    const int r8   = lane & 7;         // ldmatrix row within matrix

    const int pblock = blockIdx.x * 128;
    const int oblock = blockIdx.y * 128;

    if (tid < 128) {
        int o = oblock + tid;
        float sc = gamma[o] * rsqrtf(rvar[o] + EPSV);
        ssc[tid] = sc;
        ssh[tid] = beta[o] - rmean[o] * sc;
    }

    const uint32_t sdyn = smem_u32(dsm);

    uint32_t aoff[2];
    #pragma unroll
    for (int mt = 0; mt < 2; mt++)
        aoff[mt] = (uint32_t)(((wm * 32 + mt * 16 + (q & 1) * 8 + r8) * KST
                               + (q >> 1) * 8) * 2) + A_OFF;
    uint32_t boff[4];
    #pragma unroll
    for (int np = 0; np < 4; np++)
        boff[np] = (uint32_t)(((wn * 64 + np * 16 + (q >> 1) * 8 + r8) * KST
                               + (q & 1) * 8) * 2) + B_OFF;

    auto load_stage = [&](int ch) {
        int kc = ch * KC;
        uint32_t st = sdyn + (ch % NSTAGE) * STAGE_BYTES;
        #pragma unroll
        for (int it = 0; it < 4; it++) {
            int lin = tid + it * 256;
            int r = lin >> 3;
            int j = lin & 7;
            uint32_t d = st + r * (KST * 2) + j * 16;
            CP16(d + A_OFF, &g_Ah[(size_t)(pblock + r) * CCH + kc + j * 8]);
            CP16(d + B_OFF, &g_Wh[(size_t)(oblock + r) * CCH + kc + j * 8]);
        }
        CPCOMMIT();
    };

    float acc[2][8][4];
    #pragma unroll
    for (int mt = 0; mt < 2; mt++)
        #pragma unroll
        for (int nt = 0; nt < 8; nt++)
            #pragma unroll
            for (int rr = 0; rr < 4; rr++) acc[mt][nt][rr] = 0.0f;

    load_stage(0);
    load_stage(1);

    #pragma unroll
    for (int ch = 0; ch < 8; ch++) {
        if (ch < 7) CPWAIT(1);
        else        CPWAIT(0);
        __syncthreads();   // compute(ch-1) fully done -> buffer (ch-1)%3 free

        if (ch < 6) load_stage(ch + 2);   // writes buffer (ch+2)%3 == (ch-1)%3

        const uint32_t st = sdyn + (ch % NSTAGE) * STAGE_BYTES;
        #pragma unroll
        for (int kk = 0; kk < KC; kk += 16) {
            const uint32_t kb = st + kk * 2;
            uint32_t ah[2][4];
            uint32_t bh[8][2];
            // front-load A + two B pairs, then interleave: each later LDSM
            // issues under 4 MMAs of cover instead of serializing 6 LDSM->16 MMA
            LDSM4(ah[0][0], ah[0][1], ah[0][2], ah[0][3], kb + aoff[0]);
            LDSM4(ah[1][0], ah[1][1], ah[1][2], ah[1][3], kb + aoff[1]);
            LDSM4(bh[0][0], bh[0][1], bh[1][0], bh[1][1], kb + boff[0]);
            LDSM4(bh[2][0], bh[2][1], bh[3][0], bh[3][1], kb + boff[1]);

            MMA_F16(acc[0][0], ah[0], bh[0]);
            MMA_F16(acc[1][0], ah[1], bh[0]);
            MMA_F16(acc[0][1], ah[0], bh[1]);
            MMA_F16(acc[1][1], ah[1], bh[1]);
            LDSM4(bh[4][0], bh[4][1], bh[5][0], bh[5][1], kb + boff[2]);
            MMA_F16(acc[0][2], ah[0], bh[2]);
            MMA_F16(acc[1][2], ah[1], bh[2]);
            MMA_F16(acc[0][3], ah[0], bh[3]);
            MMA_F16(acc[1][3], ah[1], bh[3]);
            LDSM4(bh[6][0], bh[6][1], bh[7][0], bh[7][1], kb + boff[3]);
            MMA_F16(acc[0][4], ah[0], bh[4]);
            MMA_F16(acc[1][4], ah[1], bh[4]);
            MMA_F16(acc[0][5], ah[0], bh[5]);
            MMA_F16(acc[1][5], ah[1], bh[5]);
            MMA_F16(acc[0][6], ah[0], bh[6]);
            MMA_F16(acc[1][6], ah[1], bh[6]);
            MMA_F16(acc[0][7], ah[0], bh[7]);
            MMA_F16(acc[1][7], ah[1], bh[7]);
        }
    }

    // Epilogue: BN + ReLU.
    #pragma unroll
    for (int mt = 0; mt < 2; mt++) {
        int p0 = pblock + wm * 32 + mt * 16 + g8;
        int p1 = p0 + 8;
        int b0 = p0 / HW, hw0 = p0 - b0 * HW;
        int b1 = p1 / HW, hw1 = p1 - b1 * HW;
        #pragma unroll
        for (int nt = 0; nt < 8; nt++) {
            int oo  = wn * 64 + nt * 8 + tig2;
            float sc0 = ssc[oo],     sh0 = ssh[oo];
            float sc1 = ssc[oo + 1], sh1 = ssh[oo + 1];
            int o0 = oblock + oo;
            float* q00 = out + ((size_t)(b0 * CCH + o0)) * HW + hw0;
            float* q01 = out + ((size_t)(b0 * CCH + o0 + 1)) * HW + hw0;
            float* q10 = out + ((size_t)(b1 * CCH + o0)) * HW + hw1;
            float* q11 = out + ((size_t)(b1 * CCH + o0 + 1)) * HW + hw1;
            *q00 = fmaxf(fmaf(acc[mt][nt][0], sc0, sh0), 0.0f);
            *q01 = fmaxf(fmaf(acc[mt][nt][1], sc1, sh1), 0.0f);
            *q10 = fmaxf(fmaf(acc[mt][nt][2], sc0, sh0), 0.0f);
            *q11 = fmaxf(fmaf(acc[mt][nt][3], sc1, sh1), 0.0f);
        }
    }
}

extern "C" void kernel_launch(void* const* d_in, const int* in_sizes, int n_in,
                              void* d_out, int out_size)
{
    const float* x     = (const float*)d_in[0];
    const float* Wm    = (const float*)d_in[1];
    const float* gamma = (const float*)d_in[2];
    const float* beta  = (const float*)d_in[3];
    const float* rmean = (const float*)d_in[4];
    const float* rvar  = (const float*)d_in[5];
    float* out = (float*)d_out;

    cudaFuncSetAttribute(shiftconv_gemm,
                         cudaFuncAttributeMaxDynamicSharedMemorySize, SMEM_TOTAL);

    prepass_kernel<<<1024 + 784 * 8, 256>>>(x, Wm);
    dim3 grid(392, 4);
    shiftconv_gemm<<<grid, 256, SMEM_TOTAL>>>(gamma, beta, rmean, rvar, out);
}

// round 12
// speedup vs baseline: 1.4513x; 1.0367x over previous
#include <cuda_runtime.h>
#include <cuda_fp16.h>
#include <cstdint>

// ShiftConv: shift -> 1x1 conv (GEMM M=50176,N=512,K=512) -> BN -> ReLU.
// Round 12: GEMM identical to R11 (best). Prepass write phase vectorized:
// pack 2 channels per thread -> uint32 stores (half the store instructions,
// 128B/warp coalescing) instead of 2B scalar stores.

#define HDIM 28
#define HW   784
#define CCH  512
#define EPSV 1e-5f

#define MMA_F16(C, A, B) \
  asm volatile("mma.sync.aligned.m16n8k16.row.col.f32.f16.f16.f32 " \
    "{%0,%1,%2,%3}, {%4,%5,%6,%7}, {%8,%9}, {%0,%1,%2,%3};" \
    : "+f"((C)[0]), "+f"((C)[1]), "+f"((C)[2]), "+f"((C)[3]) \
    : "r"((A)[0]), "r"((A)[1]), "r"((A)[2]), "r"((A)[3]), \
      "r"((B)[0]), "r"((B)[1]))

#define LDSM4(R0, R1, R2, R3, addr) \
  asm volatile("ldmatrix.sync.aligned.m8n8.x4.shared.b16 {%0,%1,%2,%3}, [%4];" \
    : "=r"(R0), "=r"(R1), "=r"(R2), "=r"(R3) : "r"(addr))

#define CP16(dst, src) \
  asm volatile("cp.async.cg.shared.global [%0], [%1], 16;" :: "r"(dst), "l"(src))
#define CPCOMMIT() asm volatile("cp.async.commit_group;" ::: "memory")
#define CPWAIT(n)  asm volatile("cp.async.wait_group %0;" :: "n"(n) : "memory")

// K-chunk 64; smem row stride 64 real + 8 pad fp16 (144B, 16B aligned)
#define KC  64
#define KST 72
#define NSTAGE 3
#define MAT_BYTES (128 * KST * 2)          // 18432
#define A_OFF 0
#define B_OFF MAT_BYTES
#define STAGE_BYTES (2 * MAT_BYTES)        // 36864
#define SMEM_TOTAL (NSTAGE * STAGE_BYTES)  // 110592

__device__ __half g_Wh[CCH * CCH];
__device__ __half g_Ah[(size_t)50176 * CCH];   // shifted x, fp16, [p][c]

__device__ __forceinline__ uint32_t smem_u32(const void* p) {
    uint32_t a;
    asm("{ .reg .u64 t; cvta.to.shared.u64 t, %1; cvt.u32.u64 %0, t; }"
        : "=r"(a) : "l"(p));
    return a;
}

// Merged prepass. Blocks [0,1024): W fp32->fp16 convert.
// Blocks [1024, 1024+784*8): shift-gather + transpose + fp16 convert of x.
__global__ __launch_bounds__(256)
void prepass_kernel(const float* __restrict__ x, const float* __restrict__ Wm) {
    __shared__ float tile[64][65];
    __shared__ int soff[64];
    const int tid = threadIdx.x;
    const int bid = blockIdx.x;

    if (bid < 1024) {
        int i = bid * 256 + tid;
        g_Wh[i] = __float2half_rn(Wm[i]);
        return;
    }

    const int b2 = bid - 1024;
    const int p0 = (b2 >> 3) * 64;
    const int c0 = (b2 & 7) * 64;
    const int g  = c0 >> 7;

    if (tid < 64) {
        int pg = p0 + tid;
        int b  = pg / HW;
        int hw = pg - b * HW;
        int h  = hw / HDIM;
        int w  = hw - h * HDIM;
        int hs = h, ws = w;
        if      (g == 0) hs = (h + 1) % HDIM;
        else if (g == 1) hs = (h + HDIM - 1) % HDIM;
        else if (g == 2) ws = (w + 1) % HDIM;
        else             ws = (w + HDIM - 1) % HDIM;
        soff[tid] = b * (CCH * HW) + hs * HDIM + ws;
    }
    __syncthreads();
    #pragma unroll
    for (int it = 0; it < 16; it++) {       // read coalesced over p
        int lin = tid + it * 256;
        int c = lin >> 6, p = lin & 63;
        tile[c][p] = x[(size_t)(c0 + c) * HW + soff[p]];
    }
    __syncthreads();
    // write phase: 2 channels per thread, uint32 (half2) stores, coalesced
    #pragma unroll
    for (int it = 0; it < 8; it++) {
        int lin = tid + it * 256;           // 0..2047
        int p  = lin >> 5;                  // 0..63
        int cp = lin & 31;                  // channel pair 0..31
        int c  = cp * 2;
        __half h0 = __float2half_rn(tile[c][p]);
        __half h1 = __float2half_rn(tile[c + 1][p]);
        uint32_t pk = ((uint32_t)__half_as_ushort(h1) << 16) | __half_as_ushort(h0);
        *(uint32_t*)&g_Ah[(size_t)(p0 + p) * CCH + c0 + c] = pk;
    }
}

__global__ __launch_bounds__(256, 2)
void shiftconv_gemm(const float* __restrict__ gamma,
                    const float* __restrict__ beta,
                    const float* __restrict__ rmean,
                    const float* __restrict__ rvar,
                    float* __restrict__ out)
{
    extern __shared__ char dsm[];
    __shared__ float ssc[128], ssh[128];

    const int tid  = threadIdx.x;
    const int lane = tid & 31;
    const int wid  = tid >> 5;
    const int wm   = wid & 3;
    const int wn   = wid >> 2;
    const int g8   = lane >> 2;
    const int tig2 = (lane & 3) * 2;
    const int q    = lane >> 3;        // ldmatrix quad
    const int r8   = lane & 7;         // ldmatrix row within matrix

    const int pblock = blockIdx.x * 128;
    const int oblock = blockIdx.y * 128;

    if (tid < 128) {
        int o = oblock + tid;
        float sc = gamma[o] * rsqrtf(rvar[o] + EPSV);
        ssc[tid] = sc;
        ssh[tid] = beta[o] - rmean[o] * sc;
    }

    const uint32_t sdyn = smem_u32(dsm);

    uint32_t aoff[2];
    #pragma unroll
    for (int mt = 0; mt < 2; mt++)
        aoff[mt] = (uint32_t)(((wm * 32 + mt * 16 + (q & 1) * 8 + r8) * KST
                               + (q >> 1) * 8) * 2) + A_OFF;
    uint32_t boff[4];
    #pragma unroll
    for (int np = 0; np < 4; np++)
        boff[np] = (uint32_t)(((wn * 64 + np * 16 + (q >> 1) * 8 + r8) * KST
                               + (q & 1) * 8) * 2) + B_OFF;

    auto load_stage = [&](int ch) {
        int kc = ch * KC;
        uint32_t st = sdyn + (ch % NSTAGE) * STAGE_BYTES;
        #pragma unroll
        for (int it = 0; it < 4; it++) {
            int lin = tid + it * 256;
            int r = lin >> 3;
            int j = lin & 7;
            uint32_t d = st + r * (KST * 2) + j * 16;
            CP16(d + A_OFF, &g_Ah[(size_t)(pblock + r) * CCH + kc + j * 8]);
            CP16(d + B_OFF, &g_Wh[(size_t)(oblock + r) * CCH + kc + j * 8]);
        }
        CPCOMMIT();
    };

    float acc[2][8][4];
    #pragma unroll
    for (int mt = 0; mt < 2; mt++)
        #pragma unroll
        for (int nt = 0; nt < 8; nt++)
            #pragma unroll
            for (int rr = 0; rr < 4; rr++) acc[mt][nt][rr] = 0.0f;

    load_stage(0);
    load_stage(1);

    #pragma unroll
    for (int ch = 0; ch < 8; ch++) {
        if (ch < 7) CPWAIT(1);
        else        CPWAIT(0);
        __syncthreads();   // compute(ch-1) fully done -> buffer (ch-1)%3 free

        if (ch < 6) load_stage(ch + 2);   // writes buffer (ch+2)%3 == (ch-1)%3

        const uint32_t st = sdyn + (ch % NSTAGE) * STAGE_BYTES;
        #pragma unroll
        for (int kk = 0; kk < KC; kk += 16) {
            const uint32_t kb = st + kk * 2;
            uint32_t ah[2][4];
            uint32_t bh[8][2];
            LDSM4(ah[0][0], ah[0][1], ah[0][2], ah[0][3], kb + aoff[0]);
            LDSM4(ah[1][0], ah[1][1], ah[1][2], ah[1][3], kb + aoff[1]);
            LDSM4(bh[0][0], bh[0][1], bh[1][0], bh[1][1], kb + boff[0]);
            LDSM4(bh[2][0], bh[2][1], bh[3][0], bh[3][1], kb + boff[1]);

            MMA_F16(acc[0][0], ah[0], bh[0]);
            MMA_F16(acc[1][0], ah[1], bh[0]);
            MMA_F16(acc[0][1], ah[0], bh[1]);
            MMA_F16(acc[1][1], ah[1], bh[1]);
            LDSM4(bh[4][0], bh[4][1], bh[5][0], bh[5][1], kb + boff[2]);
            MMA_F16(acc[0][2], ah[0], bh[2]);
            MMA_F16(acc[1][2], ah[1], bh[2]);
            MMA_F16(acc[0][3], ah[0], bh[3]);
            MMA_F16(acc[1][3], ah[1], bh[3]);
            LDSM4(bh[6][0], bh[6][1], bh[7][0], bh[7][1], kb + boff[3]);
            MMA_F16(acc[0][4], ah[0], bh[4]);
            MMA_F16(acc[1][4], ah[1], bh[4]);
            MMA_F16(acc[0][5], ah[0], bh[5]);
            MMA_F16(acc[1][5], ah[1], bh[5]);
            MMA_F16(acc[0][6], ah[0], bh[6]);
            MMA_F16(acc[1][6], ah[1], bh[6]);
            MMA_F16(acc[0][7], ah[0], bh[7]);
            MMA_F16(acc[1][7], ah[1], bh[7]);
        }
    }

    // Epilogue: BN + ReLU.
    #pragma unroll
    for (int mt = 0; mt < 2; mt++) {
        int p0 = pblock + wm * 32 + mt * 16 + g8;
        int p1 = p0 + 8;
        int b0 = p0 / HW, hw0 = p0 - b0 * HW;
        int b1 = p1 / HW, hw1 = p1 - b1 * HW;
        #pragma unroll
        for (int nt = 0; nt < 8; nt++) {
            int oo  = wn * 64 + nt * 8 + tig2;
            float sc0 = ssc[oo],     sh0 = ssh[oo];
            float sc1 = ssc[oo + 1], sh1 = ssh[oo + 1];
            int o0 = oblock + oo;
            float* q00 = out + ((size_t)(b0 * CCH + o0)) * HW + hw0;
            float* q01 = out + ((size_t)(b0 * CCH + o0 + 1)) * HW + hw0;
            float* q10 = out + ((size_t)(b1 * CCH + o0)) * HW + hw1;
            float* q11 = out + ((size_t)(b1 * CCH + o0 + 1)) * HW + hw1;
            *q00 = fmaxf(fmaf(acc[mt][nt][0], sc0, sh0), 0.0f);
            *q01 = fmaxf(fmaf(acc[mt][nt][1], sc1, sh1), 0.0f);
            *q10 = fmaxf(fmaf(acc[mt][nt][2], sc0, sh0), 0.0f);
            *q11 = fmaxf(fmaf(acc[mt][nt][3], sc1, sh1), 0.0f);
        }
    }
}

extern "C" void kernel_launch(void* const* d_in, const int* in_sizes, int n_in,
                              void* d_out, int out_size)
{
    const float* x     = (const float*)d_in[0];
    const float* Wm    = (const float*)d_in[1];
    const float* gamma = (const float*)d_in[2];
    const float* beta  = (const float*)d_in[3];
    const float* rmean = (const float*)d_in[4];
    const float* rvar  = (const float*)d_in[5];
    float* out = (float*)d_out;

    cudaFuncSetAttribute(shiftconv_gemm,
                         cudaFuncAttributeMaxDynamicSharedMemorySize, SMEM_TOTAL);

    prepass_kernel<<<1024 + 784 * 8, 256>>>(x, Wm);
    dim3 grid(392, 4);
    shiftconv_gemm<<<grid, 256, SMEM_TOTAL>>>(gamma, beta, rmean, rvar, out);
}